// round 13
// baseline (speedup 1.0000x reference)
#include <cuda_runtime.h>
#include <math.h>

// Problem constants
#define HID  1024
#define IDIM 4096
#define NEXP 8
#define NTOK 4096           // 2*2048 tokens
#define NSLOT 3             // slot 0,1 = routed top-2, slot 2 = shared expert
#define NA (NTOK*NSLOT)     // 12288 assignment rows

// ---------------- scratch (static device globals: no allocation) -------------
__device__ float g_hbuf[(size_t)NA * IDIM];         // 201 MB: silu(g)*u per assignment
__device__ float g_ybuf[(size_t)NA * HID];          // 50 MB : down-proj per assignment
__device__ float g_rw[NTOK * 2];                    // normalized top-2 weights
__device__ float g_zsum[NTOK];                      // per-token sum(logits^2)
__device__ int   g_counts[NEXP + 1];                // tokens per expert (8 = shared)
__device__ int   g_assign_token[(NEXP + 1) * NTOK]; // gathered token index
__device__ int   g_assign_ydst [(NEXP + 1) * NTOK]; // t*3 + slot

// ----------------------- packed f32x2 FMA helpers ----------------------------
typedef unsigned long long u64t;

__device__ __forceinline__ u64t pack2(float lo, float hi) {
    u64t r;
    asm("mov.b64 %0, {%1, %2};" : "=l"(r) : "f"(lo), "f"(hi));
    return r;
}
__device__ __forceinline__ void unpack2(u64t v, float& lo, float& hi) {
    asm("mov.b64 {%0, %1}, %2;" : "=f"(lo), "=f"(hi) : "l"(v));
}
#define FMA2(acc, a, b) \
    asm("fma.rn.f32x2 %0, %1, %2, %0;" : "+l"(acc) : "l"(a), "l"(b))

// ---------------------------------- init ------------------------------------
__global__ void init_kernel() {
    int i = blockIdx.x * blockDim.x + threadIdx.x;
    if (i < NEXP + 1) g_counts[i] = (i == NEXP) ? NTOK : 0;
    if (i < NTOK) {
        g_assign_token[NEXP * NTOK + i] = i;       // shared expert: all tokens
        g_assign_ydst [NEXP * NTOK + i] = i * NSLOT + 2;
    }
}

// --------------------------------- router -----------------------------------
__global__ void router_kernel(const float* __restrict__ x,
                              const float* __restrict__ rw) {
    int warp = threadIdx.x >> 5;
    int lane = threadIdx.x & 31;
    int t = blockIdx.x * 8 + warp;
    if (t >= NTOK) return;
    const float* xr = x + (size_t)t * HID;

    float lg[NEXP];
#pragma unroll
    for (int e = 0; e < NEXP; e++) {
        const float* w = rw + e * HID;
        float s = 0.f;
        for (int h = lane; h < HID; h += 32) s = fmaf(xr[h], w[h], s);
#pragma unroll
        for (int off = 16; off > 0; off >>= 1)
            s += __shfl_xor_sync(0xffffffffu, s, off);
        lg[e] = s;
    }

    if (lane == 0) {
        float z = 0.f;
#pragma unroll
        for (int e = 0; e < NEXP; e++) z = fmaf(lg[e], lg[e], z);
        g_zsum[t] = z;

        int i1 = 0; float v1 = lg[0];
#pragma unroll
        for (int e = 1; e < NEXP; e++) if (lg[e] > v1) { v1 = lg[e]; i1 = e; }
        int i2 = -1; float v2 = -3.4e38f;
#pragma unroll
        for (int e = 0; e < NEXP; e++)
            if (e != i1 && lg[e] > v2) { v2 = lg[e]; i2 = e; }

        float e2 = expf(v2 - v1);
        float inv = 1.f / (1.f + e2);
        g_rw[t * 2 + 0] = inv;
        g_rw[t * 2 + 1] = e2 * inv;

        int p1 = atomicAdd(&g_counts[i1], 1);
        g_assign_token[i1 * NTOK + p1] = t;
        g_assign_ydst [i1 * NTOK + p1] = t * NSLOT + 0;
        int p2 = atomicAdd(&g_counts[i2], 1);
        g_assign_token[i2 * NTOK + p2] = t;
        g_assign_ydst [i2 * NTOK + p2] = t * NSLOT + 1;
    }
}

// ------------------------ GEMM1: fused gate+up + SwiGLU -----------------------
// tile 128(M) x 64(N) x 8(K), 256 threads, 8x4 microtile, packed f32x2 FMA
__global__ __launch_bounds__(256, 2) void gemm1_kernel(
    const float* __restrict__ x,
    const float* __restrict__ gate_w, const float* __restrict__ up_w,
    const float* __restrict__ sh_gate, const float* __restrict__ sh_up) {

    int e  = blockIdx.y >> 5;
    int m0 = (blockIdx.y & 31) << 7;
    int count = g_counts[e];
    if (m0 >= count) return;
    int n0 = blockIdx.x << 6;

    const float* Wg = (e < NEXP) ? gate_w + (size_t)e * IDIM * HID : sh_gate;
    const float* Wu = (e < NEXP) ? up_w   + (size_t)e * IDIM * HID : sh_up;
    int base = e * NTOK;

    __shared__ float As[2][8][128];
    __shared__ float Bg[2][8][64];
    __shared__ float Bu[2][8][64];
    __shared__ int rowtok[128];
    __shared__ int rowdst[128];

    int tid = threadIdx.x;
    if (tid < 128) {
        int r = m0 + tid;
        int rc = (r < count) ? r : count - 1;
        rowtok[tid] = g_assign_token[base + rc];
        rowdst[tid] = g_assign_ydst [base + rc];
    }
    __syncthreads();

    int aRow = tid >> 1, aK = (tid & 1) << 2;   // A: 128 rows x 8 k, float4/thread
    int bN   = tid >> 2, bK = (tid & 3) << 1;   // B: 64  rows x 8 k, float2/thread
    const float* aPtr = x  + (size_t)rowtok[aRow] * HID + aK;
    const float* gPtr = Wg + (size_t)(n0 + bN) * HID + bK;
    const float* uPtr = Wu + (size_t)(n0 + bN) * HID + bK;

    { // prologue: stage 0
        float4 av = *(const float4*)aPtr;
        As[0][aK+0][aRow]=av.x; As[0][aK+1][aRow]=av.y;
        As[0][aK+2][aRow]=av.z; As[0][aK+3][aRow]=av.w;
        float2 gv = *(const float2*)gPtr;
        Bg[0][bK][bN]=gv.x; Bg[0][bK+1][bN]=gv.y;
        float2 uv = *(const float2*)uPtr;
        Bu[0][bK][bN]=uv.x; Bu[0][bK+1][bN]=uv.y;
    }
    __syncthreads();

    // packed accumulators: cg/cu[i] -> 2 pairs each (4 n-columns)
    u64t cg[8][2], cu[8][2];
#pragma unroll
    for (int i = 0; i < 8; i++)
#pragma unroll
        for (int j = 0; j < 2; j++) { cg[i][j] = 0ull; cu[i][j] = 0ull; }

    int ty = tid >> 4, tx = tid & 15;
    int s = 0;
    for (int k0 = 0; k0 < HID; k0 += 8) {
        float4 av; float2 gv, uv;
        bool more = (k0 + 8 < HID);
        if (more) {
            av = *(const float4*)(aPtr + k0 + 8);
            gv = *(const float2*)(gPtr + k0 + 8);
            uv = *(const float2*)(uPtr + k0 + 8);
        }
#pragma unroll
        for (int kk = 0; kk < 8; kk++) {
            float4 a0 = *(const float4*)&As[s][kk][ty * 8];
            float4 a1 = *(const float4*)&As[s][kk][ty * 8 + 4];
            // B pairs straight out of smem as 64-bit words (consecutive cols)
            ulonglong2 bgq = *(const ulonglong2*)&Bg[s][kk][tx * 4];
            ulonglong2 buq = *(const ulonglong2*)&Bu[s][kk][tx * 4];
            u64t am2[8];
            am2[0]=pack2(a0.x,a0.x); am2[1]=pack2(a0.y,a0.y);
            am2[2]=pack2(a0.z,a0.z); am2[3]=pack2(a0.w,a0.w);
            am2[4]=pack2(a1.x,a1.x); am2[5]=pack2(a1.y,a1.y);
            am2[6]=pack2(a1.z,a1.z); am2[7]=pack2(a1.w,a1.w);
#pragma unroll
            for (int i = 0; i < 8; i++) {
                FMA2(cg[i][0], am2[i], bgq.x);
                FMA2(cg[i][1], am2[i], bgq.y);
                FMA2(cu[i][0], am2[i], buq.x);
                FMA2(cu[i][1], am2[i], buq.y);
            }
        }
        if (more) {
            int tn = s ^ 1;
            As[tn][aK+0][aRow]=av.x; As[tn][aK+1][aRow]=av.y;
            As[tn][aK+2][aRow]=av.z; As[tn][aK+3][aRow]=av.w;
            Bg[tn][bK][bN]=gv.x; Bg[tn][bK+1][bN]=gv.y;
            Bu[tn][bK][bN]=uv.x; Bu[tn][bK+1][bN]=uv.y;
        }
        __syncthreads();
        s ^= 1;
    }

#pragma unroll
    for (int i = 0; i < 8; i++) {
        int m = m0 + ty * 8 + i;
        if (m < count) {
            int dst = rowdst[ty * 8 + i];
            float g0,g1,g2,g3,u0,u1,u2,u3;
            unpack2(cg[i][0], g0, g1); unpack2(cg[i][1], g2, g3);
            unpack2(cu[i][0], u0, u1); unpack2(cu[i][1], u2, u3);
            float4 hv;
            hv.x = g0 / (1.f + expf(-g0)) * u0;
            hv.y = g1 / (1.f + expf(-g1)) * u1;
            hv.z = g2 / (1.f + expf(-g2)) * u2;
            hv.w = g3 / (1.f + expf(-g3)) * u3;
            *(float4*)(g_hbuf + (size_t)dst * IDIM + n0 + tx * 4) = hv;
        }
    }
}

// ------------------------------ GEMM2: down ----------------------------------
// tile 128x128x8, 256 threads, 8x8 microtile, packed f32x2 FMA
__global__ __launch_bounds__(256, 2) void gemm2_kernel(
    const float* __restrict__ down_w, const float* __restrict__ sh_down) {

    int e  = blockIdx.y >> 5;
    int m0 = (blockIdx.y & 31) << 7;
    int count = g_counts[e];
    if (m0 >= count) return;
    int n0 = blockIdx.x << 7;
    const float* Wd = (e < NEXP) ? down_w + (size_t)e * HID * IDIM : sh_down;
    int base = e * NTOK;

    __shared__ float As[2][8][128];
    __shared__ float Bs[2][8][128];
    __shared__ int ydst_s[128];

    int tid = threadIdx.x;
    if (tid < 128) {
        int r = m0 + tid;
        int rc = (r < count) ? r : count - 1;
        ydst_s[tid] = g_assign_ydst[base + rc];
    }
    __syncthreads();

    int aRow = tid >> 1, aK = (tid & 1) << 2;
    int bN   = tid >> 1, bK = (tid & 1) << 2;
    const float* aPtr = g_hbuf + (size_t)ydst_s[aRow] * IDIM + aK;
    const float* bPtr = Wd + (size_t)(n0 + bN) * IDIM + bK;

    { // prologue
        float4 av = *(const float4*)aPtr;
        As[0][aK+0][aRow]=av.x; As[0][aK+1][aRow]=av.y;
        As[0][aK+2][aRow]=av.z; As[0][aK+3][aRow]=av.w;
        float4 bv = *(const float4*)bPtr;
        Bs[0][bK+0][bN]=bv.x; Bs[0][bK+1][bN]=bv.y;
        Bs[0][bK+2][bN]=bv.z; Bs[0][bK+3][bN]=bv.w;
    }
    __syncthreads();

    // packed accumulators: 8 m-rows x 4 column-pairs (8 n-columns)
    u64t acc[8][4];
#pragma unroll
    for (int i = 0; i < 8; i++)
#pragma unroll
        for (int j = 0; j < 4; j++) acc[i][j] = 0ull;

    int ty = tid >> 4, tx = tid & 15;
    int s = 0;
    for (int k0 = 0; k0 < IDIM; k0 += 8) {
        float4 av, bv;
        bool more = (k0 + 8 < IDIM);
        if (more) {
            av = *(const float4*)(aPtr + k0 + 8);
            bv = *(const float4*)(bPtr + k0 + 8);
        }
#pragma unroll
        for (int kk = 0; kk < 8; kk++) {
            float4 a0 = *(const float4*)&As[s][kk][ty * 8];
            float4 a1 = *(const float4*)&As[s][kk][ty * 8 + 4];
            ulonglong2 bq0 = *(const ulonglong2*)&Bs[s][kk][tx * 8];
            ulonglong2 bq1 = *(const ulonglong2*)&Bs[s][kk][tx * 8 + 4];
            u64t am2[8];
            am2[0]=pack2(a0.x,a0.x); am2[1]=pack2(a0.y,a0.y);
            am2[2]=pack2(a0.z,a0.z); am2[3]=pack2(a0.w,a0.w);
            am2[4]=pack2(a1.x,a1.x); am2[5]=pack2(a1.y,a1.y);
            am2[6]=pack2(a1.z,a1.z); am2[7]=pack2(a1.w,a1.w);
#pragma unroll
            for (int i = 0; i < 8; i++) {
                FMA2(acc[i][0], am2[i], bq0.x);
                FMA2(acc[i][1], am2[i], bq0.y);
                FMA2(acc[i][2], am2[i], bq1.x);
                FMA2(acc[i][3], am2[i], bq1.y);
            }
        }
        if (more) {
            int tn = s ^ 1;
            As[tn][aK+0][aRow]=av.x; As[tn][aK+1][aRow]=av.y;
            As[tn][aK+2][aRow]=av.z; As[tn][aK+3][aRow]=av.w;
            Bs[tn][bK+0][bN]=bv.x; Bs[tn][bK+1][bN]=bv.y;
            Bs[tn][bK+2][bN]=bv.z; Bs[tn][bK+3][bN]=bv.w;
        }
        __syncthreads();
        s ^= 1;
    }

#pragma unroll
    for (int i = 0; i < 8; i++) {
        int m = m0 + ty * 8 + i;
        if (m < count) {
            int dst = ydst_s[ty * 8 + i];
            float* yp = g_ybuf + (size_t)dst * HID + n0 + tx * 8;
            float4 o0, o1;
            unpack2(acc[i][0], o0.x, o0.y); unpack2(acc[i][1], o0.z, o0.w);
            unpack2(acc[i][2], o1.x, o1.y); unpack2(acc[i][3], o1.z, o1.w);
            *(float4*)(yp)     = o0;
            *(float4*)(yp + 4) = o1;
        }
    }
}

// ------------------------------- combine -------------------------------------
__global__ void combine_kernel(float* __restrict__ out) {
    int idx = blockIdx.x * blockDim.x + threadIdx.x;  // over NTOK * HID/4
    int t  = idx >> 8;           // 256 float4 per token
    int h4 = (idx & 255) << 2;
    const float* yb = g_ybuf + (size_t)t * NSLOT * HID;
    float w0 = g_rw[t * 2], w1 = g_rw[t * 2 + 1];
    float4 y0 = *(const float4*)(yb + h4);
    float4 y1 = *(const float4*)(yb + HID + h4);
    float4 y2 = *(const float4*)(yb + 2 * HID + h4);
    float4 o;
    o.x = fmaf(w0, y0.x, fmaf(w1, y1.x, y2.x));
    o.y = fmaf(w0, y0.y, fmaf(w1, y1.y, y2.y));
    o.z = fmaf(w0, y0.z, fmaf(w1, y1.z, y2.z));
    o.w = fmaf(w0, y0.w, fmaf(w1, y1.w, y2.w));
    *(float4*)(out + (size_t)t * HID + h4) = o;
}

// ------------------------------- aux loss ------------------------------------
__global__ void aux_kernel(float* __restrict__ out, int out_size) {
    __shared__ float red[1024];
    int tid = threadIdx.x;
    float s = 0.f;
    for (int t = tid; t < NTOK; t += 1024) s += g_zsum[t];
    red[tid] = s;
    __syncthreads();
    for (int o = 512; o > 0; o >>= 1) {
        if (tid < o) red[tid] += red[tid + o];
        __syncthreads();
    }
    if (tid == 0) {
        float z = red[0] / (float)NTOK;                       // router z-loss
        float tot = (float)(NTOK * 2 + NTOK);                 // sum(loads) = 12288
        float ideal = 1.f / 9.f;
        float lb = 0.f;
        for (int e = 0; e < NEXP; e++) {
            float ln = (float)g_counts[e] / tot;
            float d = ln - ideal; lb += d * d;
        }
        { float ln = (float)NTOK / tot; float d = ln - ideal; lb += d * d; }
        lb /= 9.f;
        out[out_size - 1] = 0.01f * lb + 0.01f * z;
    }
}

// ------------------------------ entry point ----------------------------------
extern "C" void kernel_launch(void* const* d_in, const int* in_sizes, int n_in,
                              void* d_out, int out_size) {
    const float* x        = (const float*)d_in[0];
    const float* router_w = (const float*)d_in[1];
    const float* gate_w   = (const float*)d_in[2];
    const float* up_w     = (const float*)d_in[3];
    const float* down_w   = (const float*)d_in[4];
    const float* sh_gate  = (const float*)d_in[5];
    const float* sh_up    = (const float*)d_in[6];
    const float* sh_down  = (const float*)d_in[7];
    float* out = (float*)d_out;

    init_kernel<<<(NTOK + 255) / 256, 256>>>();
    router_kernel<<<NTOK / 8, 256>>>(x, router_w);

    dim3 g1(IDIM / 64, (NEXP + 1) * 32);   // 64 n-tiles x (9 experts * 32 m-tiles)
    gemm1_kernel<<<g1, 256>>>(x, gate_w, up_w, sh_gate, sh_up);

    dim3 g2(HID / 128, (NEXP + 1) * 32);   // 8 n-tiles x 288 m-tiles
    gemm2_kernel<<<g2, 256>>>(down_w, sh_down);

    combine_kernel<<<(NTOK * HID / 4) / 256, 256>>>(out);
    aux_kernel<<<1, 1024>>>(out, out_size);
}

// round 14
// speedup vs baseline: 1.0239x; 1.0239x over previous
#include <cuda_runtime.h>
#include <math.h>

// Problem constants
#define HID  1024
#define IDIM 4096
#define NEXP 8
#define NTOK 4096           // 2*2048 tokens
#define NSLOT 3             // slot 0,1 = routed top-2, slot 2 = shared expert
#define NA (NTOK*NSLOT)     // 12288 assignment rows

// ---------------- scratch (static device globals: no allocation) -------------
__device__ float g_hbuf[(size_t)NA * IDIM];         // 201 MB: silu(g)*u per assignment
__device__ float g_ybuf[(size_t)NA * HID];          // 50 MB : down-proj per assignment
__device__ float g_rw[NTOK * 2];                    // normalized top-2 weights
__device__ float g_zsum[NTOK];                      // per-token sum(logits^2)
__device__ int   g_counts[NEXP + 1];                // tokens per expert (8 = shared)
__device__ int   g_assign_token[(NEXP + 1) * NTOK]; // gathered token index
__device__ int   g_assign_ydst [(NEXP + 1) * NTOK]; // t*3 + slot

// ----------------------- packed f32x2 FMA helpers ----------------------------
typedef unsigned long long u64t;

__device__ __forceinline__ u64t pack2dup(float v) {
    u64t r;
    asm("mov.b64 %0, {%1, %1};" : "=l"(r) : "f"(v));
    return r;
}
__device__ __forceinline__ void unpack2(u64t v, float& lo, float& hi) {
    asm("mov.b64 {%0, %1}, %2;" : "=f"(lo), "=f"(hi) : "l"(v));
}
#define FMA2(acc, a, b) \
    asm("fma.rn.f32x2 %0, %1, %2, %0;" : "+l"(acc) : "l"(a), "l"(b))

// ---------------------------------- init ------------------------------------
__global__ void init_kernel() {
    int i = blockIdx.x * blockDim.x + threadIdx.x;
    if (i < NEXP + 1) g_counts[i] = (i == NEXP) ? NTOK : 0;
    if (i < NTOK) {
        g_assign_token[NEXP * NTOK + i] = i;       // shared expert: all tokens
        g_assign_ydst [NEXP * NTOK + i] = i * NSLOT + 2;
    }
}

// --------------------------------- router -----------------------------------
__global__ void router_kernel(const float* __restrict__ x,
                              const float* __restrict__ rw) {
    int warp = threadIdx.x >> 5;
    int lane = threadIdx.x & 31;
    int t = blockIdx.x * 8 + warp;
    if (t >= NTOK) return;
    const float* xr = x + (size_t)t * HID;

    float lg[NEXP];
#pragma unroll
    for (int e = 0; e < NEXP; e++) {
        const float* w = rw + e * HID;
        float s = 0.f;
        for (int h = lane; h < HID; h += 32) s = fmaf(xr[h], w[h], s);
#pragma unroll
        for (int off = 16; off > 0; off >>= 1)
            s += __shfl_xor_sync(0xffffffffu, s, off);
        lg[e] = s;
    }

    if (lane == 0) {
        float z = 0.f;
#pragma unroll
        for (int e = 0; e < NEXP; e++) z = fmaf(lg[e], lg[e], z);
        g_zsum[t] = z;

        int i1 = 0; float v1 = lg[0];
#pragma unroll
        for (int e = 1; e < NEXP; e++) if (lg[e] > v1) { v1 = lg[e]; i1 = e; }
        int i2 = -1; float v2 = -3.4e38f;
#pragma unroll
        for (int e = 0; e < NEXP; e++)
            if (e != i1 && lg[e] > v2) { v2 = lg[e]; i2 = e; }

        float e2 = expf(v2 - v1);
        float inv = 1.f / (1.f + e2);
        g_rw[t * 2 + 0] = inv;
        g_rw[t * 2 + 1] = e2 * inv;

        int p1 = atomicAdd(&g_counts[i1], 1);
        g_assign_token[i1 * NTOK + p1] = t;
        g_assign_ydst [i1 * NTOK + p1] = t * NSLOT + 0;
        int p2 = atomicAdd(&g_counts[i2], 1);
        g_assign_token[i2 * NTOK + p2] = t;
        g_assign_ydst [i2 * NTOK + p2] = t * NSLOT + 1;
    }
}

// ------------------------ GEMM1: fused gate+up + SwiGLU -----------------------
// tile 128(M) x 128(N) x 8(K), 256 threads, 16x(4+4) microtile, packed FMA2.
// Warp layout: ty = tid>>5 (one ty per warp -> A smem reads are pure broadcast),
// tx = tid&31 covers 128 N-columns as 4 per thread (for both gate and up).
__global__ __launch_bounds__(256, 1) void gemm1_kernel(
    const float* __restrict__ x,
    const float* __restrict__ gate_w, const float* __restrict__ up_w,
    const float* __restrict__ sh_gate, const float* __restrict__ sh_up) {

    int e  = blockIdx.y >> 5;
    int m0 = (blockIdx.y & 31) << 7;
    int count = g_counts[e];
    if (m0 >= count) return;
    int n0 = blockIdx.x << 7;

    const float* Wg = (e < NEXP) ? gate_w + (size_t)e * IDIM * HID : sh_gate;
    const float* Wu = (e < NEXP) ? up_w   + (size_t)e * IDIM * HID : sh_up;
    int base = e * NTOK;

    __shared__ float As[2][8][128];
    __shared__ float Bg[2][8][128];
    __shared__ float Bu[2][8][128];
    __shared__ int rowtok[128];
    __shared__ int rowdst[128];

    int tid = threadIdx.x;
    if (tid < 128) {
        int r = m0 + tid;
        int rc = (r < count) ? r : count - 1;
        rowtok[tid] = g_assign_token[base + rc];
        rowdst[tid] = g_assign_ydst [base + rc];
    }
    __syncthreads();

    // global staging: 2 threads per row, float4 each (k 0..3 / 4..7)
    int aRow = tid >> 1, aK = (tid & 1) << 2;
    const float* aPtr = x  + (size_t)rowtok[aRow] * HID + aK;
    const float* gPtr = Wg + (size_t)(n0 + aRow) * HID + aK;
    const float* uPtr = Wu + (size_t)(n0 + aRow) * HID + aK;

    { // prologue: stage 0
        float4 av = *(const float4*)aPtr;
        As[0][aK+0][aRow]=av.x; As[0][aK+1][aRow]=av.y;
        As[0][aK+2][aRow]=av.z; As[0][aK+3][aRow]=av.w;
        float4 gv = *(const float4*)gPtr;
        Bg[0][aK+0][aRow]=gv.x; Bg[0][aK+1][aRow]=gv.y;
        Bg[0][aK+2][aRow]=gv.z; Bg[0][aK+3][aRow]=gv.w;
        float4 uv = *(const float4*)uPtr;
        Bu[0][aK+0][aRow]=uv.x; Bu[0][aK+1][aRow]=uv.y;
        Bu[0][aK+2][aRow]=uv.z; Bu[0][aK+3][aRow]=uv.w;
    }
    __syncthreads();

    // acc: 16 m-rows x 2 col-pairs (4 cols) for gate and up
    u64t cg[16][2], cu[16][2];
#pragma unroll
    for (int i = 0; i < 16; i++)
#pragma unroll
        for (int j = 0; j < 2; j++) { cg[i][j] = 0ull; cu[i][j] = 0ull; }

    int ty = tid >> 5, tx = tid & 31;
    int s = 0;
    for (int k0 = 0; k0 < HID; k0 += 8) {
        float4 av, gv, uv;
        bool more = (k0 + 8 < HID);
        if (more) {
            av = *(const float4*)(aPtr + k0 + 8);
            gv = *(const float4*)(gPtr + k0 + 8);
            uv = *(const float4*)(uPtr + k0 + 8);
        }
#pragma unroll
        for (int kk = 0; kk < 8; kk++) {
            // B pairs straight out of smem (consecutive cols, conflict-free)
            ulonglong2 bgq = *(const ulonglong2*)&Bg[s][kk][tx * 4];
            ulonglong2 buq = *(const ulonglong2*)&Bu[s][kk][tx * 4];
            // A broadcast reads, processed in two halves of 8 rows to cap regs
#pragma unroll
            for (int h = 0; h < 2; h++) {
                float4 a0 = *(const float4*)&As[s][kk][ty * 16 + h * 8];
                float4 a1 = *(const float4*)&As[s][kk][ty * 16 + h * 8 + 4];
                u64t am2[8];
                am2[0]=pack2dup(a0.x); am2[1]=pack2dup(a0.y);
                am2[2]=pack2dup(a0.z); am2[3]=pack2dup(a0.w);
                am2[4]=pack2dup(a1.x); am2[5]=pack2dup(a1.y);
                am2[6]=pack2dup(a1.z); am2[7]=pack2dup(a1.w);
#pragma unroll
                for (int i = 0; i < 8; i++) {
                    int r = h * 8 + i;
                    FMA2(cg[r][0], am2[i], bgq.x);
                    FMA2(cg[r][1], am2[i], bgq.y);
                    FMA2(cu[r][0], am2[i], buq.x);
                    FMA2(cu[r][1], am2[i], buq.y);
                }
            }
        }
        if (more) {
            int tn = s ^ 1;
            As[tn][aK+0][aRow]=av.x; As[tn][aK+1][aRow]=av.y;
            As[tn][aK+2][aRow]=av.z; As[tn][aK+3][aRow]=av.w;
            Bg[tn][aK+0][aRow]=gv.x; Bg[tn][aK+1][aRow]=gv.y;
            Bg[tn][aK+2][aRow]=gv.z; Bg[tn][aK+3][aRow]=gv.w;
            Bu[tn][aK+0][aRow]=uv.x; Bu[tn][aK+1][aRow]=uv.y;
            Bu[tn][aK+2][aRow]=uv.z; Bu[tn][aK+3][aRow]=uv.w;
        }
        __syncthreads();
        s ^= 1;
    }

#pragma unroll
    for (int i = 0; i < 16; i++) {
        int m = m0 + ty * 16 + i;
        if (m < count) {
            int dst = rowdst[ty * 16 + i];
            float g0,g1,g2,g3,u0,u1,u2,u3;
            unpack2(cg[i][0], g0, g1); unpack2(cg[i][1], g2, g3);
            unpack2(cu[i][0], u0, u1); unpack2(cu[i][1], u2, u3);
            float4 hv;
            hv.x = g0 / (1.f + expf(-g0)) * u0;
            hv.y = g1 / (1.f + expf(-g1)) * u1;
            hv.z = g2 / (1.f + expf(-g2)) * u2;
            hv.w = g3 / (1.f + expf(-g3)) * u3;
            *(float4*)(g_hbuf + (size_t)dst * IDIM + n0 + tx * 4) = hv;
        }
    }
}

// ------------------------------ GEMM2: down ----------------------------------
// tile 128(M) x 256(N) x 8(K), 256 threads, 16x8 microtile, packed FMA2.
// Warp layout: ty = tid>>5 (A reads broadcast), tx = tid&31 covers 256 N cols.
__global__ __launch_bounds__(256, 1) void gemm2_kernel(
    const float* __restrict__ down_w, const float* __restrict__ sh_down) {

    int e  = blockIdx.y >> 5;
    int m0 = (blockIdx.y & 31) << 7;
    int count = g_counts[e];
    if (m0 >= count) return;
    int n0 = blockIdx.x << 8;
    const float* Wd = (e < NEXP) ? down_w + (size_t)e * HID * IDIM : sh_down;
    int base = e * NTOK;

    __shared__ float As[2][8][128];
    __shared__ float Bs[2][8][256];
    __shared__ int ydst_s[128];

    int tid = threadIdx.x;
    if (tid < 128) {
        int r = m0 + tid;
        int rc = (r < count) ? r : count - 1;
        ydst_s[tid] = g_assign_ydst[base + rc];
    }
    __syncthreads();

    // staging: A 2 threads/row (float4), B 1 thread/row (2x float4 over 8 k)
    int aRow = tid >> 1, aK = (tid & 1) << 2;
    const float* aPtr = g_hbuf + (size_t)ydst_s[aRow] * IDIM + aK;
    const float* bPtr = Wd + (size_t)(n0 + tid) * IDIM;

    { // prologue
        float4 av = *(const float4*)aPtr;
        As[0][aK+0][aRow]=av.x; As[0][aK+1][aRow]=av.y;
        As[0][aK+2][aRow]=av.z; As[0][aK+3][aRow]=av.w;
        float4 b0 = *(const float4*)bPtr;
        float4 b1 = *(const float4*)(bPtr + 4);
        Bs[0][0][tid]=b0.x; Bs[0][1][tid]=b0.y; Bs[0][2][tid]=b0.z; Bs[0][3][tid]=b0.w;
        Bs[0][4][tid]=b1.x; Bs[0][5][tid]=b1.y; Bs[0][6][tid]=b1.z; Bs[0][7][tid]=b1.w;
    }
    __syncthreads();

    // acc: 16 m-rows x 4 col-pairs (8 n-cols)
    u64t acc[16][4];
#pragma unroll
    for (int i = 0; i < 16; i++)
#pragma unroll
        for (int j = 0; j < 4; j++) acc[i][j] = 0ull;

    int ty = tid >> 5, tx = tid & 31;
    int s = 0;
    for (int k0 = 0; k0 < IDIM; k0 += 8) {
        float4 av, b0, b1;
        bool more = (k0 + 8 < IDIM);
        if (more) {
            av = *(const float4*)(aPtr + k0 + 8);
            b0 = *(const float4*)(bPtr + k0 + 8);
            b1 = *(const float4*)(bPtr + k0 + 12);
        }
#pragma unroll
        for (int kk = 0; kk < 8; kk++) {
            ulonglong2 bq0 = *(const ulonglong2*)&Bs[s][kk][tx * 8];
            ulonglong2 bq1 = *(const ulonglong2*)&Bs[s][kk][tx * 8 + 4];
#pragma unroll
            for (int h = 0; h < 2; h++) {
                float4 a0 = *(const float4*)&As[s][kk][ty * 16 + h * 8];
                float4 a1 = *(const float4*)&As[s][kk][ty * 16 + h * 8 + 4];
                u64t am2[8];
                am2[0]=pack2dup(a0.x); am2[1]=pack2dup(a0.y);
                am2[2]=pack2dup(a0.z); am2[3]=pack2dup(a0.w);
                am2[4]=pack2dup(a1.x); am2[5]=pack2dup(a1.y);
                am2[6]=pack2dup(a1.z); am2[7]=pack2dup(a1.w);
#pragma unroll
                for (int i = 0; i < 8; i++) {
                    int r = h * 8 + i;
                    FMA2(acc[r][0], am2[i], bq0.x);
                    FMA2(acc[r][1], am2[i], bq0.y);
                    FMA2(acc[r][2], am2[i], bq1.x);
                    FMA2(acc[r][3], am2[i], bq1.y);
                }
            }
        }
        if (more) {
            int tn = s ^ 1;
            As[tn][aK+0][aRow]=av.x; As[tn][aK+1][aRow]=av.y;
            As[tn][aK+2][aRow]=av.z; As[tn][aK+3][aRow]=av.w;
            Bs[tn][0][tid]=b0.x; Bs[tn][1][tid]=b0.y; Bs[tn][2][tid]=b0.z; Bs[tn][3][tid]=b0.w;
            Bs[tn][4][tid]=b1.x; Bs[tn][5][tid]=b1.y; Bs[tn][6][tid]=b1.z; Bs[tn][7][tid]=b1.w;
        }
        __syncthreads();
        s ^= 1;
    }

#pragma unroll
    for (int i = 0; i < 16; i++) {
        int m = m0 + ty * 16 + i;
        if (m < count) {
            int dst = ydst_s[ty * 16 + i];
            float* yp = g_ybuf + (size_t)dst * HID + n0 + tx * 8;
            float4 o0, o1;
            unpack2(acc[i][0], o0.x, o0.y); unpack2(acc[i][1], o0.z, o0.w);
            unpack2(acc[i][2], o1.x, o1.y); unpack2(acc[i][3], o1.z, o1.w);
            *(float4*)(yp)     = o0;
            *(float4*)(yp + 4) = o1;
        }
    }
}

// ------------------------------- combine -------------------------------------
__global__ void combine_kernel(float* __restrict__ out) {
    int idx = blockIdx.x * blockDim.x + threadIdx.x;  // over NTOK * HID/4
    int t  = idx >> 8;           // 256 float4 per token
    int h4 = (idx & 255) << 2;
    const float* yb = g_ybuf + (size_t)t * NSLOT * HID;
    float w0 = g_rw[t * 2], w1 = g_rw[t * 2 + 1];
    float4 y0 = *(const float4*)(yb + h4);
    float4 y1 = *(const float4*)(yb + HID + h4);
    float4 y2 = *(const float4*)(yb + 2 * HID + h4);
    float4 o;
    o.x = fmaf(w0, y0.x, fmaf(w1, y1.x, y2.x));
    o.y = fmaf(w0, y0.y, fmaf(w1, y1.y, y2.y));
    o.z = fmaf(w0, y0.z, fmaf(w1, y1.z, y2.z));
    o.w = fmaf(w0, y0.w, fmaf(w1, y1.w, y2.w));
    *(float4*)(out + (size_t)t * HID + h4) = o;
}

// ------------------------------- aux loss ------------------------------------
__global__ void aux_kernel(float* __restrict__ out, int out_size) {
    __shared__ float red[1024];
    int tid = threadIdx.x;
    float s = 0.f;
    for (int t = tid; t < NTOK; t += 1024) s += g_zsum[t];
    red[tid] = s;
    __syncthreads();
    for (int o = 512; o > 0; o >>= 1) {
        if (tid < o) red[tid] += red[tid + o];
        __syncthreads();
    }
    if (tid == 0) {
        float z = red[0] / (float)NTOK;                       // router z-loss
        float tot = (float)(NTOK * 2 + NTOK);                 // sum(loads) = 12288
        float ideal = 1.f / 9.f;
        float lb = 0.f;
        for (int e = 0; e < NEXP; e++) {
            float ln = (float)g_counts[e] / tot;
            float d = ln - ideal; lb += d * d;
        }
        { float ln = (float)NTOK / tot; float d = ln - ideal; lb += d * d; }
        lb /= 9.f;
        out[out_size - 1] = 0.01f * lb + 0.01f * z;
    }
}

// ------------------------------ entry point ----------------------------------
extern "C" void kernel_launch(void* const* d_in, const int* in_sizes, int n_in,
                              void* d_out, int out_size) {
    const float* x        = (const float*)d_in[0];
    const float* router_w = (const float*)d_in[1];
    const float* gate_w   = (const float*)d_in[2];
    const float* up_w     = (const float*)d_in[3];
    const float* down_w   = (const float*)d_in[4];
    const float* sh_gate  = (const float*)d_in[5];
    const float* sh_up    = (const float*)d_in[6];
    const float* sh_down  = (const float*)d_in[7];
    float* out = (float*)d_out;

    init_kernel<<<(NTOK + 255) / 256, 256>>>();
    router_kernel<<<NTOK / 8, 256>>>(x, router_w);

    dim3 g1(IDIM / 128, (NEXP + 1) * 32);  // 32 n-tiles x (9 experts * 32 m-tiles)
    gemm1_kernel<<<g1, 256>>>(x, gate_w, up_w, sh_gate, sh_up);

    dim3 g2(HID / 256, (NEXP + 1) * 32);   // 4 n-tiles x 288 m-tiles
    gemm2_kernel<<<g2, 256>>>(down_w, sh_down);

    combine_kernel<<<(NTOK * HID / 4) / 256, 256>>>(out);
    aux_kernel<<<1, 1024>>>(out, out_size);
}

// round 15
// speedup vs baseline: 1.0251x; 1.0011x over previous
#include <cuda_runtime.h>
#include <math.h>

// Problem constants
#define HID  1024
#define IDIM 4096
#define NEXP 8
#define NTOK 4096           // 2*2048 tokens
#define NSLOT 3             // slot 0,1 = routed top-2, slot 2 = shared expert
#define NA (NTOK*NSLOT)     // 12288 assignment rows

// ---------------- scratch (static device globals: no allocation) -------------
__device__ float g_hbuf[(size_t)NA * IDIM];         // 201 MB: silu(g)*u per assignment
__device__ float g_ybuf[(size_t)NA * HID];          // 50 MB : down-proj per assignment
__device__ float g_rw[NTOK * 2];                    // normalized top-2 weights
__device__ float g_zsum[NTOK];                      // per-token sum(logits^2)
__device__ int   g_counts[NEXP + 1];                // tokens per expert (8 = shared)
__device__ int   g_assign_token[(NEXP + 1) * NTOK]; // gathered token index
__device__ int   g_assign_ydst [(NEXP + 1) * NTOK]; // t*3 + slot

// ----------------------- packed f32x2 FMA helpers ----------------------------
typedef unsigned long long u64t;

__device__ __forceinline__ u64t pack2dup(float v) {
    u64t r;
    asm("mov.b64 %0, {%1, %1};" : "=l"(r) : "f"(v));
    return r;
}
__device__ __forceinline__ void unpack2(u64t v, float& lo, float& hi) {
    asm("mov.b64 {%0, %1}, %2;" : "=f"(lo), "=f"(hi) : "l"(v));
}
#define FMA2(acc, a, b) \
    asm("fma.rn.f32x2 %0, %1, %2, %0;" : "+l"(acc) : "l"(a), "l"(b))

// ---------------------------------- init ------------------------------------
__global__ void init_kernel() {
    int i = blockIdx.x * blockDim.x + threadIdx.x;
    if (i < NEXP + 1) g_counts[i] = (i == NEXP) ? NTOK : 0;
    if (i < NTOK) {
        g_assign_token[NEXP * NTOK + i] = i;       // shared expert: all tokens
        g_assign_ydst [NEXP * NTOK + i] = i * NSLOT + 2;
    }
}

// --------------------------------- router -----------------------------------
__global__ void router_kernel(const float* __restrict__ x,
                              const float* __restrict__ rw) {
    int warp = threadIdx.x >> 5;
    int lane = threadIdx.x & 31;
    int t = blockIdx.x * 8 + warp;
    if (t >= NTOK) return;
    const float* xr = x + (size_t)t * HID;

    float lg[NEXP];
#pragma unroll
    for (int e = 0; e < NEXP; e++) {
        const float* w = rw + e * HID;
        float s = 0.f;
        for (int h = lane; h < HID; h += 32) s = fmaf(xr[h], w[h], s);
#pragma unroll
        for (int off = 16; off > 0; off >>= 1)
            s += __shfl_xor_sync(0xffffffffu, s, off);
        lg[e] = s;
    }

    if (lane == 0) {
        float z = 0.f;
#pragma unroll
        for (int e = 0; e < NEXP; e++) z = fmaf(lg[e], lg[e], z);
        g_zsum[t] = z;

        int i1 = 0; float v1 = lg[0];
#pragma unroll
        for (int e = 1; e < NEXP; e++) if (lg[e] > v1) { v1 = lg[e]; i1 = e; }
        int i2 = -1; float v2 = -3.4e38f;
#pragma unroll
        for (int e = 0; e < NEXP; e++)
            if (e != i1 && lg[e] > v2) { v2 = lg[e]; i2 = e; }

        float e2 = expf(v2 - v1);
        float inv = 1.f / (1.f + e2);
        g_rw[t * 2 + 0] = inv;
        g_rw[t * 2 + 1] = e2 * inv;

        int p1 = atomicAdd(&g_counts[i1], 1);
        g_assign_token[i1 * NTOK + p1] = t;
        g_assign_ydst [i1 * NTOK + p1] = t * NSLOT + 0;
        int p2 = atomicAdd(&g_counts[i2], 1);
        g_assign_token[i2 * NTOK + p2] = t;
        g_assign_ydst [i2 * NTOK + p2] = t * NSLOT + 1;
    }
}

// ------------------------ GEMM1: fused gate+up + SwiGLU -----------------------
// tile 128(M) x 128(N) x 8(K), 256 threads, 16x(4+4) microtile, packed FMA2.
// Warp layout: ty = tid>>5 (one ty per warp -> A smem reads are pure broadcast),
// tx = tid&31 covers 128 N-columns as 4 per thread (for both gate and up).
__global__ __launch_bounds__(256, 1) void gemm1_kernel(
    const float* __restrict__ x,
    const float* __restrict__ gate_w, const float* __restrict__ up_w,
    const float* __restrict__ sh_gate, const float* __restrict__ sh_up) {

    int e  = blockIdx.y >> 5;
    int m0 = (blockIdx.y & 31) << 7;
    int count = g_counts[e];
    if (m0 >= count) return;
    int n0 = blockIdx.x << 7;

    const float* Wg = (e < NEXP) ? gate_w + (size_t)e * IDIM * HID : sh_gate;
    const float* Wu = (e < NEXP) ? up_w   + (size_t)e * IDIM * HID : sh_up;
    int base = e * NTOK;

    __shared__ float As[2][8][128];
    __shared__ float Bg[2][8][128];
    __shared__ float Bu[2][8][128];
    __shared__ int rowtok[128];
    __shared__ int rowdst[128];

    int tid = threadIdx.x;
    if (tid < 128) {
        int r = m0 + tid;
        int rc = (r < count) ? r : count - 1;
        rowtok[tid] = g_assign_token[base + rc];
        rowdst[tid] = g_assign_ydst [base + rc];
    }
    __syncthreads();

    // global staging: 2 threads per row, float4 each (k 0..3 / 4..7)
    int aRow = tid >> 1, aK = (tid & 1) << 2;
    const float* aPtr = x  + (size_t)rowtok[aRow] * HID + aK;
    const float* gPtr = Wg + (size_t)(n0 + aRow) * HID + aK;
    const float* uPtr = Wu + (size_t)(n0 + aRow) * HID + aK;

    { // prologue: stage 0
        float4 av = *(const float4*)aPtr;
        As[0][aK+0][aRow]=av.x; As[0][aK+1][aRow]=av.y;
        As[0][aK+2][aRow]=av.z; As[0][aK+3][aRow]=av.w;
        float4 gv = *(const float4*)gPtr;
        Bg[0][aK+0][aRow]=gv.x; Bg[0][aK+1][aRow]=gv.y;
        Bg[0][aK+2][aRow]=gv.z; Bg[0][aK+3][aRow]=gv.w;
        float4 uv = *(const float4*)uPtr;
        Bu[0][aK+0][aRow]=uv.x; Bu[0][aK+1][aRow]=uv.y;
        Bu[0][aK+2][aRow]=uv.z; Bu[0][aK+3][aRow]=uv.w;
    }
    __syncthreads();

    // acc: 16 m-rows x 2 col-pairs (4 cols) for gate and up
    u64t cg[16][2], cu[16][2];
#pragma unroll
    for (int i = 0; i < 16; i++)
#pragma unroll
        for (int j = 0; j < 2; j++) { cg[i][j] = 0ull; cu[i][j] = 0ull; }

    int ty = tid >> 5, tx = tid & 31;
    int s = 0;
    for (int k0 = 0; k0 < HID; k0 += 8) {
        float4 av, gv, uv;
        bool more = (k0 + 8 < HID);
        if (more) {
            av = *(const float4*)(aPtr + k0 + 8);
            gv = *(const float4*)(gPtr + k0 + 8);
            uv = *(const float4*)(uPtr + k0 + 8);
        }
#pragma unroll
        for (int kk = 0; kk < 8; kk++) {
            // B pairs straight out of smem (consecutive cols, conflict-free)
            ulonglong2 bgq = *(const ulonglong2*)&Bg[s][kk][tx * 4];
            ulonglong2 buq = *(const ulonglong2*)&Bu[s][kk][tx * 4];
            // A broadcast reads, processed in two halves of 8 rows to cap regs
#pragma unroll
            for (int h = 0; h < 2; h++) {
                float4 a0 = *(const float4*)&As[s][kk][ty * 16 + h * 8];
                float4 a1 = *(const float4*)&As[s][kk][ty * 16 + h * 8 + 4];
                u64t am2[8];
                am2[0]=pack2dup(a0.x); am2[1]=pack2dup(a0.y);
                am2[2]=pack2dup(a0.z); am2[3]=pack2dup(a0.w);
                am2[4]=pack2dup(a1.x); am2[5]=pack2dup(a1.y);
                am2[6]=pack2dup(a1.z); am2[7]=pack2dup(a1.w);
#pragma unroll
                for (int i = 0; i < 8; i++) {
                    int r = h * 8 + i;
                    FMA2(cg[r][0], am2[i], bgq.x);
                    FMA2(cg[r][1], am2[i], bgq.y);
                    FMA2(cu[r][0], am2[i], buq.x);
                    FMA2(cu[r][1], am2[i], buq.y);
                }
            }
        }
        if (more) {
            int tn = s ^ 1;
            As[tn][aK+0][aRow]=av.x; As[tn][aK+1][aRow]=av.y;
            As[tn][aK+2][aRow]=av.z; As[tn][aK+3][aRow]=av.w;
            Bg[tn][aK+0][aRow]=gv.x; Bg[tn][aK+1][aRow]=gv.y;
            Bg[tn][aK+2][aRow]=gv.z; Bg[tn][aK+3][aRow]=gv.w;
            Bu[tn][aK+0][aRow]=uv.x; Bu[tn][aK+1][aRow]=uv.y;
            Bu[tn][aK+2][aRow]=uv.z; Bu[tn][aK+3][aRow]=uv.w;
        }
        __syncthreads();
        s ^= 1;
    }

#pragma unroll
    for (int i = 0; i < 16; i++) {
        int m = m0 + ty * 16 + i;
        if (m < count) {
            int dst = rowdst[ty * 16 + i];
            float g0,g1,g2,g3,u0,u1,u2,u3;
            unpack2(cg[i][0], g0, g1); unpack2(cg[i][1], g2, g3);
            unpack2(cu[i][0], u0, u1); unpack2(cu[i][1], u2, u3);
            float4 hv;
            hv.x = g0 / (1.f + expf(-g0)) * u0;
            hv.y = g1 / (1.f + expf(-g1)) * u1;
            hv.z = g2 / (1.f + expf(-g2)) * u2;
            hv.w = g3 / (1.f + expf(-g3)) * u3;
            *(float4*)(g_hbuf + (size_t)dst * IDIM + n0 + tx * 4) = hv;
        }
    }
}

// ------------------------------ GEMM2: down ----------------------------------
// tile 128(M) x 256(N) x 8(K), 256 threads, 16x8 microtile, packed FMA2.
// Warp layout: ty = tid>>5 (A reads broadcast), tx = tid&31 covers 256 N cols.
__global__ __launch_bounds__(256, 1) void gemm2_kernel(
    const float* __restrict__ down_w, const float* __restrict__ sh_down) {

    int e  = blockIdx.y >> 5;
    int m0 = (blockIdx.y & 31) << 7;
    int count = g_counts[e];
    if (m0 >= count) return;
    int n0 = blockIdx.x << 8;
    const float* Wd = (e < NEXP) ? down_w + (size_t)e * HID * IDIM : sh_down;
    int base = e * NTOK;

    __shared__ float As[2][8][128];
    __shared__ float Bs[2][8][256];
    __shared__ int ydst_s[128];

    int tid = threadIdx.x;
    if (tid < 128) {
        int r = m0 + tid;
        int rc = (r < count) ? r : count - 1;
        ydst_s[tid] = g_assign_ydst[base + rc];
    }
    __syncthreads();

    // staging: A 2 threads/row (float4), B 1 thread/row (2x float4 over 8 k)
    int aRow = tid >> 1, aK = (tid & 1) << 2;
    const float* aPtr = g_hbuf + (size_t)ydst_s[aRow] * IDIM + aK;
    const float* bPtr = Wd + (size_t)(n0 + tid) * IDIM;

    { // prologue
        float4 av = *(const float4*)aPtr;
        As[0][aK+0][aRow]=av.x; As[0][aK+1][aRow]=av.y;
        As[0][aK+2][aRow]=av.z; As[0][aK+3][aRow]=av.w;
        float4 b0 = *(const float4*)bPtr;
        float4 b1 = *(const float4*)(bPtr + 4);
        Bs[0][0][tid]=b0.x; Bs[0][1][tid]=b0.y; Bs[0][2][tid]=b0.z; Bs[0][3][tid]=b0.w;
        Bs[0][4][tid]=b1.x; Bs[0][5][tid]=b1.y; Bs[0][6][tid]=b1.z; Bs[0][7][tid]=b1.w;
    }
    __syncthreads();

    // acc: 16 m-rows x 4 col-pairs (8 n-cols)
    u64t acc[16][4];
#pragma unroll
    for (int i = 0; i < 16; i++)
#pragma unroll
        for (int j = 0; j < 4; j++) acc[i][j] = 0ull;

    int ty = tid >> 5, tx = tid & 31;
    int s = 0;
    for (int k0 = 0; k0 < IDIM; k0 += 8) {
        float4 av, b0, b1;
        bool more = (k0 + 8 < IDIM);
        if (more) {
            av = *(const float4*)(aPtr + k0 + 8);
            b0 = *(const float4*)(bPtr + k0 + 8);
            b1 = *(const float4*)(bPtr + k0 + 12);
        }
#pragma unroll
        for (int kk = 0; kk < 8; kk++) {
            ulonglong2 bq0 = *(const ulonglong2*)&Bs[s][kk][tx * 8];
            ulonglong2 bq1 = *(const ulonglong2*)&Bs[s][kk][tx * 8 + 4];
#pragma unroll
            for (int h = 0; h < 2; h++) {
                float4 a0 = *(const float4*)&As[s][kk][ty * 16 + h * 8];
                float4 a1 = *(const float4*)&As[s][kk][ty * 16 + h * 8 + 4];
                u64t am2[8];
                am2[0]=pack2dup(a0.x); am2[1]=pack2dup(a0.y);
                am2[2]=pack2dup(a0.z); am2[3]=pack2dup(a0.w);
                am2[4]=pack2dup(a1.x); am2[5]=pack2dup(a1.y);
                am2[6]=pack2dup(a1.z); am2[7]=pack2dup(a1.w);
#pragma unroll
                for (int i = 0; i < 8; i++) {
                    int r = h * 8 + i;
                    FMA2(acc[r][0], am2[i], bq0.x);
                    FMA2(acc[r][1], am2[i], bq0.y);
                    FMA2(acc[r][2], am2[i], bq1.x);
                    FMA2(acc[r][3], am2[i], bq1.y);
                }
            }
        }
        if (more) {
            int tn = s ^ 1;
            As[tn][aK+0][aRow]=av.x; As[tn][aK+1][aRow]=av.y;
            As[tn][aK+2][aRow]=av.z; As[tn][aK+3][aRow]=av.w;
            Bs[tn][0][tid]=b0.x; Bs[tn][1][tid]=b0.y; Bs[tn][2][tid]=b0.z; Bs[tn][3][tid]=b0.w;
            Bs[tn][4][tid]=b1.x; Bs[tn][5][tid]=b1.y; Bs[tn][6][tid]=b1.z; Bs[tn][7][tid]=b1.w;
        }
        __syncthreads();
        s ^= 1;
    }

#pragma unroll
    for (int i = 0; i < 16; i++) {
        int m = m0 + ty * 16 + i;
        if (m < count) {
            int dst = ydst_s[ty * 16 + i];
            float* yp = g_ybuf + (size_t)dst * HID + n0 + tx * 8;
            float4 o0, o1;
            unpack2(acc[i][0], o0.x, o0.y); unpack2(acc[i][1], o0.z, o0.w);
            unpack2(acc[i][2], o1.x, o1.y); unpack2(acc[i][3], o1.z, o1.w);
            *(float4*)(yp)     = o0;
            *(float4*)(yp + 4) = o1;
        }
    }
}

// ------------------------------- combine -------------------------------------
__global__ void combine_kernel(float* __restrict__ out) {
    int idx = blockIdx.x * blockDim.x + threadIdx.x;  // over NTOK * HID/4
    int t  = idx >> 8;           // 256 float4 per token
    int h4 = (idx & 255) << 2;
    const float* yb = g_ybuf + (size_t)t * NSLOT * HID;
    float w0 = g_rw[t * 2], w1 = g_rw[t * 2 + 1];
    float4 y0 = *(const float4*)(yb + h4);
    float4 y1 = *(const float4*)(yb + HID + h4);
    float4 y2 = *(const float4*)(yb + 2 * HID + h4);
    float4 o;
    o.x = fmaf(w0, y0.x, fmaf(w1, y1.x, y2.x));
    o.y = fmaf(w0, y0.y, fmaf(w1, y1.y, y2.y));
    o.z = fmaf(w0, y0.z, fmaf(w1, y1.z, y2.z));
    o.w = fmaf(w0, y0.w, fmaf(w1, y1.w, y2.w));
    *(float4*)(out + (size_t)t * HID + h4) = o;
}

// ------------------------------- aux loss ------------------------------------
__global__ void aux_kernel(float* __restrict__ out, int out_size) {
    __shared__ float red[1024];
    int tid = threadIdx.x;
    float s = 0.f;
    for (int t = tid; t < NTOK; t += 1024) s += g_zsum[t];
    red[tid] = s;
    __syncthreads();
    for (int o = 512; o > 0; o >>= 1) {
        if (tid < o) red[tid] += red[tid + o];
        __syncthreads();
    }
    if (tid == 0) {
        float z = red[0] / (float)NTOK;                       // router z-loss
        float tot = (float)(NTOK * 2 + NTOK);                 // sum(loads) = 12288
        float ideal = 1.f / 9.f;
        float lb = 0.f;
        for (int e = 0; e < NEXP; e++) {
            float ln = (float)g_counts[e] / tot;
            float d = ln - ideal; lb += d * d;
        }
        { float ln = (float)NTOK / tot; float d = ln - ideal; lb += d * d; }
        lb /= 9.f;
        out[out_size - 1] = 0.01f * lb + 0.01f * z;
    }
}

// ------------------------------ entry point ----------------------------------
extern "C" void kernel_launch(void* const* d_in, const int* in_sizes, int n_in,
                              void* d_out, int out_size) {
    const float* x        = (const float*)d_in[0];
    const float* router_w = (const float*)d_in[1];
    const float* gate_w   = (const float*)d_in[2];
    const float* up_w     = (const float*)d_in[3];
    const float* down_w   = (const float*)d_in[4];
    const float* sh_gate  = (const float*)d_in[5];
    const float* sh_up    = (const float*)d_in[6];
    const float* sh_down  = (const float*)d_in[7];
    float* out = (float*)d_out;

    init_kernel<<<(NTOK + 255) / 256, 256>>>();
    router_kernel<<<NTOK / 8, 256>>>(x, router_w);

    dim3 g1(IDIM / 128, (NEXP + 1) * 32);  // 32 n-tiles x (9 experts * 32 m-tiles)
    gemm1_kernel<<<g1, 256>>>(x, gate_w, up_w, sh_gate, sh_up);

    dim3 g2(HID / 256, (NEXP + 1) * 32);   // 4 n-tiles x 288 m-tiles
    gemm2_kernel<<<g2, 256>>>(down_w, sh_down);

    combine_kernel<<<(NTOK * HID / 4) / 256, 256>>>(out);
    aux_kernel<<<1, 1024>>>(out, out_size);
}